// round 14
// baseline (speedup 1.0000x reference)
#include <cuda_runtime.h>
#include <math.h>

#define NB   16
#define HH   160
#define WW   160
#define HW   (HH*WW)
#define TOPK 32
#define WCAP 32
#define NV   68
#define RAD2DEG 57.29577951308232f
#define THR  0.99f

// fallback scratch only (never touched on the fast path)
__device__ float g_peaks[NB*HW];

// ---- dynamic shared layout (bytes), non-aliased ----
#define CBT_PITCH 212
#define SP_PITCH  101
#define SV_PITCH  205
#define SL_PITCH  137
#define S_CK    0                          // u64[32*32]  8192
#define S_CBT   (S_CK + 32*WCAP*8)
#define S_SP    (S_CBT + 80*CBT_PITCH*4)
#define S_SV    (S_SP  + TOPK*SP_PITCH*4)
#define S_SL    (S_SV  + TOPK*SV_PITCH*4)
#define DSM_SIZE (S_SL + TOPK*SL_PITCH*4)  // 8192+67840+12928+26240+17536 = 132,736

#define PACK_DUP(out, f) asm("mov.b64 %0, {%1, %1};" : "=l"(out) : "r"(__float_as_uint(f)))
#define FMA2(acc, bb, cc)  asm("fma.rn.f32x2 %0, %1, %2, %0;" : "+l"(acc) : "l"(bb), "l"(cc))
#define UNPACK2(lo, hi, in) asm("mov.b64 {%0, %1}, %2;" : "=r"(lo), "=r"(hi) : "l"(in))

__global__ void __launch_bounds__(1024) fused_kernel(
    const float* __restrict__ hms,
    const float* __restrict__ pmaps,
    const float* __restrict__ oshapes,
    const float* __restrict__ pms,
    const float* __restrict__ u_base,
    const float* __restrict__ shp_base,
    const float* __restrict__ exp_base,
    float* __restrict__ out)
{
    extern __shared__ char dsm[];
    int b    = blockIdx.x;
    int tid  = threadIdx.x;
    int lane = tid & 31;
    int wid  = tid >> 5;
    const float* h = hms + (size_t)b * HW;

    unsigned long long* ck = (unsigned long long*)(dsm + S_CK);   // 32 regions x 32 slots
    float* cbT    = (float*)(dsm + S_CBT);
    float* sp     = (float*)(dsm + S_SP);
    float* sverts = (float*)(dsm + S_SV);
    float* slnm   = (float*)(dsm + S_SL);

    __shared__ int   wcnt[32];
    __shared__ float s_sc[TOPK];
    __shared__ int   s_ix[TOPK];
    __shared__ float sbb[TOPK][5];
    __shared__ float spose[TOPK][3];
    __shared__ float sob[TOPK][4], sosc[TOPK];
    __shared__ int   svalid[TOPK], smatch[TOPK];
    __shared__ unsigned rowm[TOPK];
    __shared__ unsigned ssupp;
    __shared__ int   s_fast;
    __shared__ float rv[32];
    __shared__ int   rid[32];

    // ---- pre-scan: stage transposed basis (overlaps scan's DRAM latency) ----
    if (tid < 32) wcnt[tid] = 0;
    for (int i = tid; i < 204 * 50; i += 1024) {
        int r = i / 50, k = i - r * 50;
        cbT[k * CBT_PITCH + r] = shp_base[i];
    }
    for (int i = tid; i < 204 * 29; i += 1024) {
        int r = i / 29, k = i - r * 29;
        cbT[(50 + k) * CBT_PITCH + r] = exp_base[i];
    }
    if (tid < 204) cbT[79 * CBT_PITCH + tid] = u_base[tid];
    __syncthreads();

    // ---- peak scan: center test + warp-uniform rare branch, per-warp buffers ----
    const float NEG = -1e30f;
    for (int c = tid; c < HW / 4; c += 1024) {
        int px = c * 4;
        float4 a1 = *(const float4*)(h + px);
        float mx = fmaxf(fmaxf(a1.x, a1.y), fmaxf(a1.z, a1.w));
        unsigned bal = __ballot_sync(0xffffffffu, mx > THR);
        if (bal) {                            // warp-uniform rare branch
            int y  = px / WW;
            int x0 = px - y * WW;
            int ym = (y > 0)      ? y - 1 : y;
            int yp = (y < HH - 1) ? y + 1 : y;
            float4 a0 = *(const float4*)(h + (size_t)ym * WW + x0);
            float4 a2 = *(const float4*)(h + (size_t)yp * WW + x0);
            float m0 = fmaxf(a1.x, fmaxf(a0.x, a2.x));
            float m1 = fmaxf(a1.y, fmaxf(a0.y, a2.y));
            float m2 = fmaxf(a1.z, fmaxf(a0.z, a2.z));
            float m3 = fmaxf(a1.w, fmaxf(a0.w, a2.w));
            float lm = NEG, rm = NEG;
            if (x0 > 0) {
                int xl = x0 - 1;
                lm = fmaxf(h[(size_t)y * WW + xl], fmaxf(h[(size_t)ym * WW + xl], h[(size_t)yp * WW + xl]));
            }
            if (x0 + 4 < WW) {
                int xr = x0 + 4;
                rm = fmaxf(h[(size_t)y * WW + xr], fmaxf(h[(size_t)ym * WW + xr], h[(size_t)yp * WW + xr]));
            }
            bool c0 = (a1.x > THR) && (fmaxf(lm, fmaxf(m0, m1)) == a1.x);
            bool c1 = (a1.y > THR) && (fmaxf(m0, fmaxf(m1, m2)) == a1.y);
            bool c2 = (a1.z > THR) && (fmaxf(m1, fmaxf(m2, m3)) == a1.z);
            bool c3 = (a1.w > THR) && (fmaxf(m2, fmaxf(m3, rm)) == a1.w);
            // per-warp buffer: atomics spread across 32 addresses
            if (c0) { int pos = atomicAdd(&wcnt[wid], 1); if (pos < WCAP)
                ck[wid * WCAP + pos] = ((unsigned long long)__float_as_uint(a1.x) << 20) | (unsigned)(HW - (px + 0)); }
            if (c1) { int pos = atomicAdd(&wcnt[wid], 1); if (pos < WCAP)
                ck[wid * WCAP + pos] = ((unsigned long long)__float_as_uint(a1.y) << 20) | (unsigned)(HW - (px + 1)); }
            if (c2) { int pos = atomicAdd(&wcnt[wid], 1); if (pos < WCAP)
                ck[wid * WCAP + pos] = ((unsigned long long)__float_as_uint(a1.z) << 20) | (unsigned)(HW - (px + 2)); }
            if (c3) { int pos = atomicAdd(&wcnt[wid], 1); if (pos < WCAP)
                ck[wid * WCAP + pos] = ((unsigned long long)__float_as_uint(a1.w) << 20) | (unsigned)(HW - (px + 3)); }
        }
    }
    __syncthreads();

    // validate: total >= 32 and no per-warp overflow
    if (tid < 32) {
        int c = wcnt[lane];
        int total = c, ovf = (c > WCAP) ? 1 : 0;
        #pragma unroll
        for (int o = 16; o; o >>= 1) {
            total += __shfl_down_sync(0xffffffffu, total, o);
            ovf   |= __shfl_down_sync(0xffffffffu, ovf, o);
        }
        if (lane == 0) s_fast = (total >= TOPK && !ovf) ? 1 : 0;
    }
    __syncthreads();

    if (s_fast) {
        // rank-select: thread (w=wid, i=lane) ranks key i of warp w's region
        if (lane < wcnt[wid]) {
            unsigned long long kt = ck[wid * WCAP + lane];
            int rank = 0;
            for (int w = 0; w < 32; w++) {
                int cw = wcnt[w];
                const unsigned long long* r = &ck[w * WCAP];
                for (int i = 0; i < cw; i++) rank += (r[i] > kt) ? 1 : 0;
            }
            if (rank < TOPK) {
                s_sc[rank] = __uint_as_float((unsigned)(kt >> 20));
                s_ix[rank] = HW - (int)(kt & 0xFFFFFull);
            }
        }
    } else {
        // robust fallback: materialize full peak map, 32 block argmax rounds
        float* pk = g_peaks + (size_t)b * HW;
        for (int i = tid; i < HW; i += 1024) {
            int y = i / WW, x = i - y * WW;
            float v = h[i], m = v;
            int y0 = (y > 0) ? y - 1 : y, y1 = (y < HH - 1) ? y + 1 : y;
            int x0 = (x > 0) ? x - 1 : x, x1 = (x < WW - 1) ? x + 1 : x;
            for (int yy = y0; yy <= y1; yy++)
                for (int xx = x0; xx <= x1; xx++)
                    m = fmaxf(m, h[yy * WW + xx]);
            pk[i] = (v == m) ? v : 0.0f;
        }
        __syncthreads();
        for (int r = 0; r < TOPK; r++) {
            float bv = -2.0f; int bi = 0x3fffffff;
            for (int i = tid; i < HW; i += 1024) {
                float v = pk[i];
                if (v > bv || (v == bv && i < bi)) { bv = v; bi = i; }
            }
            #pragma unroll
            for (int o = 16; o; o >>= 1) {
                float v2 = __shfl_down_sync(0xffffffffu, bv, o);
                int   i2 = __shfl_down_sync(0xffffffffu, bi, o);
                if (v2 > bv || (v2 == bv && i2 < bi)) { bv = v2; bi = i2; }
            }
            if (lane == 0) { rv[wid] = bv; rid[wid] = bi; }
            __syncthreads();
            if (tid < 32) {
                bv = rv[lane]; bi = rid[lane];
                #pragma unroll
                for (int o = 16; o; o >>= 1) {
                    float v2 = __shfl_down_sync(0xffffffffu, bv, o);
                    int   i2 = __shfl_down_sync(0xffffffffu, bi, o);
                    if (v2 > bv || (v2 == bv && i2 < bi)) { bv = v2; bi = i2; }
                }
                if (lane == 0) { s_sc[r] = bv; s_ix[r] = bi; pk[bi] = -1.0f; }
            }
            __syncthreads();
        }
    }
    __syncthreads();

    // ================= geometry =================
    for (int e = tid; e < TOPK * 91; e += 1024) {
        int det = e / 91, j = e - det * 91;
        float v = fmaf(pmaps[((size_t)b * HW + (size_t)s_ix[det]) * 91 + j],
                       pms[91 + j], pms[j]);
        int slot = (j < 12) ? (84 + j) : ((j < 62) ? (j - 12) : (52 + (j - 62)));
        sp[det * SP_PITCH + slot] = v;
    }
    __syncthreads();

    // verts: warp w owns rows [8w, 8w+8), lane = det; packed f32x2 FMA
    if (wid < 26) {
        int r0 = wid * 8;
        const float* cp = &sp[lane * SP_PITCH];
        const ulonglong2* urow = (const ulonglong2*)&cbT[79 * CBT_PITCH + r0];
        ulonglong2 u0 = urow[0], u1 = urow[1];
        unsigned long long acc0 = u0.x, acc1 = u0.y, acc2 = u1.x, acc3 = u1.y;
        #pragma unroll 4
        for (int k = 0; k < 79; k++) {
            int slot = k + ((k >= 50) ? 2 : 0);
            float c = cp[slot];
            unsigned long long cd;
            PACK_DUP(cd, c);
            const ulonglong2* brow = (const ulonglong2*)&cbT[k * CBT_PITCH + r0];
            ulonglong2 b0 = brow[0], b1 = brow[1];
            FMA2(acc0, b0.x, cd);
            FMA2(acc1, b0.y, cd);
            FMA2(acc2, b1.x, cd);
            FMA2(acc3, b1.y, cd);
        }
        unsigned av[8];
        UNPACK2(av[0], av[1], acc0);
        UNPACK2(av[2], av[3], acc1);
        UNPACK2(av[4], av[5], acc2);
        UNPACK2(av[6], av[7], acc3);
        #pragma unroll
        for (int q = 0; q < 8; q++) {
            int r = r0 + q;
            if (r < 204) sverts[lane * SV_PITCH + r] = __uint_as_float(av[q]);
        }
    }
    __syncthreads();

    // ---- fused projection + bbox + pose: warp = det ----
    {
        int det = wid;
        const float* p = &sp[det * SP_PITCH + 84];
        float s  = p[0];
        float R00 = p[1], R01 = p[2], R02 = p[3];
        float R10 = p[5], R11 = p[6], R12 = p[7];
        int idx = s_ix[det];
        int ys = idx / WW, xs = idx - (idx / WW) * WW;
        float ry = oshapes[b * 2 + 0] * (1.0f / 160.0f);
        float rx = oshapes[b * 2 + 1] * (1.0f / 160.0f);
        float coy = (float)ys * ry;
        float cox = (float)xs * rx;

        float ymn = 1e30f, ymx = -1e30f, xmn = 1e30f, xmx = -1e30f;
        #pragma unroll
        for (int q = 0; q < 3; q++) {
            int v = lane + q * 32;
            if (v < NV) {
                const float* vt = &sverts[det * SV_PITCH + 3 * v];
                float vx = vt[0], vy = vt[1], vz = vt[2];
                float l0 = s * (vx * R00 + vy * R01 + vz * R02);
                float l1 = s * (vx * R10 + vy * R11 + vz * R12);
                float yy = l1 + coy;
                float xx = l0 + cox;
                slnm[det * SL_PITCH + 2 * v]     = yy;
                slnm[det * SL_PITCH + 2 * v + 1] = xx;
                ymn = fminf(ymn, yy); ymx = fmaxf(ymx, yy);
                xmn = fminf(xmn, xx); xmx = fmaxf(xmx, xx);
            }
        }
        #pragma unroll
        for (int o = 16; o; o >>= 1) {
            ymn = fminf(ymn, __shfl_down_sync(0xffffffffu, ymn, o));
            ymx = fmaxf(ymx, __shfl_down_sync(0xffffffffu, ymx, o));
            xmn = fminf(xmn, __shfl_down_sync(0xffffffffu, xmn, o));
            xmx = fmaxf(xmx, __shfl_down_sync(0xffffffffu, xmx, o));
        }
        if (lane == 0) {
            bool mask = s_sc[det] > 0.5f;
            if (mask) { sbb[det][0] = ymn; sbb[det][1] = xmn; sbb[det][2] = ymx; sbb[det][3] = xmx; sbb[det][4] = s_sc[det]; }
            else      { sbb[det][0] = -1.0f; sbb[det][1] = -1.0f; sbb[det][2] = -1.0f; sbb[det][3] = -1.0f; sbb[det][4] = -1.0f; }

            float yaw   = asinf(-p[9]) * RAD2DEG;
            float cyw   = cosf(yaw);   // faithful: cos of yaw in DEGREES
            float pitch = atan2f(p[10] / cyw, p[11] / cyw) * RAD2DEG;
            float roll  = atan2f(R10 / cyw, R00 / cyw) * RAD2DEG;
            spose[det][0] = pitch; spose[det][1] = yaw; spose[det][2] = roll;
        }
    }
    __syncthreads();

    // ================= NMS (parallel row-masks) + packing =================
    if (tid < TOPK) { sosc[tid] = 0.0f; sob[tid][0] = 0.0f; sob[tid][1] = 0.0f; sob[tid][2] = 0.0f; sob[tid][3] = 0.0f; }
    if (tid >= 32 && tid < 64) {
        int i = tid - 32;
        float i0 = sbb[i][0], i1 = sbb[i][1], i2 = sbb[i][2], i3 = sbb[i][3];
        float ia = (i2 - i0) * (i3 - i1);
        unsigned m = 0;
        for (int j = 0; j < TOPK; j++) {
            float j0 = sbb[j][0], j1 = sbb[j][1], j2 = sbb[j][2], j3 = sbb[j][3];
            float ja = (j2 - j0) * (j3 - j1);
            float yy = fminf(i2, j2) - fmaxf(i0, j0);
            float xx = fminf(i3, j3) - fmaxf(i1, j1);
            float inter = fmaxf(yy, 0.0f) * fmaxf(xx, 0.0f);
            float uni   = ia + ja - inter;
            float iou   = inter / fmaxf(uni, 1e-8f);
            if (iou > 0.4f && j > i) m |= (1u << j);
        }
        rowm[i] = m;
    }
    __syncthreads();
    if (tid == 0) {
        unsigned supp = 0u;
        for (int i = 0; i < TOPK; i++)
            if (!((supp >> i) & 1u)) supp |= rowm[i];
        ssupp = supp;
    }
    __syncthreads();
    if (tid < 32) {
        unsigned supp = ssupp;
        bool keep = !((supp >> lane) & 1u);
        unsigned km = __ballot_sync(0xffffffffu, keep);
        int rank = __popc(km & ((1u << lane) - 1u));
        if (keep) {
            sob[rank][0] = sbb[lane][0]; sob[rank][1] = sbb[lane][1];
            sob[rank][2] = sbb[lane][2]; sob[rank][3] = sbb[lane][3];
            sosc[rank]   = sbb[lane][4];
        }
    }
    __syncthreads();

    const float INF = __int_as_float(0x7f800000);
    if (tid < TOPK) {
        bool valid = true;
        #pragma unroll
        for (int c = 0; c < 4; c++) {
            float v = sob[tid][c];
            if (v == -1.0f || v == 0.0f) { v = INF; valid = false; }
            sob[tid][c] = v;
        }
        svalid[tid] = valid ? 1 : 0;
    }
    __syncthreads();
    if (tid < TOPK) {
        float sn = s_sc[tid];
        int m = 0;
        for (int k = 0; k < TOPK; k++)
            if (svalid[k] && sosc[k] == sn) m = 1;
        smatch[tid] = m;
    }
    __syncthreads();

    // out_bboxes (B,32,6)
    float* ob = out + (size_t)b * TOPK * 6;
    for (int e = tid; e < TOPK * 6; e += 1024) {
        int k = e / 6, c = e - k * 6;
        ob[e] = (c < 4) ? sob[k][c] : ((c == 4) ? sosc[k] : 0.0f);
    }
    // out_lnmks (B,32,68,2)
    float* ol = out + (size_t)NB * TOPK * 6 + (size_t)b * TOPK * NV * 2;
    for (int e = tid; e < TOPK * NV * 2; e += 1024) {
        int n = e / (NV * 2), j = e - n * (NV * 2);
        float l = slnm[n * SL_PITCH + j];
        ol[e] = (smatch[n] && l != -1.0f) ? l : INF;
    }
    // out_pose (B,32,3)
    float* op = out + (size_t)NB * TOPK * 6 + (size_t)NB * TOPK * NV * 2 + (size_t)b * TOPK * 3;
    for (int e = tid; e < TOPK * 3; e += 1024) {
        int n = e / 3, c = e - n * 3;
        float p = spose[n][c];
        op[e] = (smatch[n] && p != -1.0f) ? p : INF;
    }
}

extern "C" void kernel_launch(void* const* d_in, const int* in_sizes, int n_in,
                              void* d_out, int out_size) {
    const float* hms      = (const float*)d_in[0];
    const float* pmaps    = (const float*)d_in[1];
    const float* oshapes  = (const float*)d_in[2];
    const float* pms      = (const float*)d_in[3];
    const float* u_base   = (const float*)d_in[4];
    const float* shp_base = (const float*)d_in[5];
    const float* exp_base = (const float*)d_in[6];
    float* out = (float*)d_out;

    static int attr_done = 0;
    if (!attr_done) {
        cudaFuncSetAttribute(fused_kernel, cudaFuncAttributeMaxDynamicSharedMemorySize, DSM_SIZE);
        attr_done = 1;
    }
    fused_kernel<<<NB, 1024, DSM_SIZE>>>(hms, pmaps, oshapes, pms, u_base, shp_base, exp_base, out);
}

// round 15
// speedup vs baseline: 1.1979x; 1.1979x over previous
#include <cuda_runtime.h>
#include <math.h>

#define NB   16
#define HH   160
#define WW   160
#define HW   (HH*WW)
#define TOPK 32
#define CAPK 2048
#define NV   68
#define RAD2DEG 57.29577951308232f
#define THR  0.99f

// fallback scratch only (never touched on the fast path)
__device__ float g_peaks[NB*HW];

// ---- dynamic shared layout (bytes), non-aliased ----
#define CBT_PITCH 212
#define SP_PITCH  101
#define SV_PITCH  205
#define SL_PITCH  137
#define S_CK    0                          // u64[2048]   16384
#define S_CBT   (S_CK + CAPK*8)
#define S_SP    (S_CBT + 80*CBT_PITCH*4)
#define S_SV    (S_SP  + TOPK*SP_PITCH*4)
#define S_SL    (S_SV  + TOPK*SV_PITCH*4)
#define DSM_SIZE (S_SL + TOPK*SL_PITCH*4)  // 140,928

#define PACK_DUP(out, f) asm("mov.b64 %0, {%1, %1};" : "=l"(out) : "r"(__float_as_uint(f)))
#define FMA2(acc, bb, cc)  asm("fma.rn.f32x2 %0, %1, %2, %0;" : "+l"(acc) : "l"(bb), "l"(cc))
#define UNPACK2(lo, hi, in) asm("mov.b64 {%0, %1}, %2;" : "=r"(lo), "=r"(hi) : "l"(in))

__global__ void __launch_bounds__(1024) fused_kernel(
    const float* __restrict__ hms,
    const float* __restrict__ pmaps,
    const float* __restrict__ oshapes,
    const float* __restrict__ pms,
    const float* __restrict__ u_base,
    const float* __restrict__ shp_base,
    const float* __restrict__ exp_base,
    float* __restrict__ out)
{
    extern __shared__ char dsm[];
    int b    = blockIdx.x;
    int tid  = threadIdx.x;
    int lane = tid & 31;
    int wid  = tid >> 5;
    const float* h = hms + (size_t)b * HW;

    unsigned long long* ck = (unsigned long long*)(dsm + S_CK);
    float* cbT    = (float*)(dsm + S_CBT);
    float* sp     = (float*)(dsm + S_SP);
    float* sverts = (float*)(dsm + S_SV);
    float* slnm   = (float*)(dsm + S_SL);

    __shared__ float s_sc[TOPK];
    __shared__ int   s_ix[TOPK];
    __shared__ float sbb[TOPK][5];
    __shared__ float spose[TOPK][3];
    __shared__ float sob[TOPK][4], sosc[TOPK];
    __shared__ int   svalid[TOPK], smatch[TOPK];
    __shared__ unsigned rowm[TOPK];
    __shared__ unsigned ssupp;
    __shared__ int   s_cnt;
    __shared__ float rv[32];
    __shared__ int   rid[32];

    // ---- pre-scan: stage transposed basis (overlaps scan's DRAM latency) ----
    if (tid == 0) s_cnt = 0;
    for (int i = tid; i < 204 * 50; i += 1024) {
        int r = i / 50, k = i - r * 50;
        cbT[k * CBT_PITCH + r] = shp_base[i];
    }
    for (int i = tid; i < 204 * 29; i += 1024) {
        int r = i / 29, k = i - r * 29;
        cbT[(50 + k) * CBT_PITCH + r] = exp_base[i];
    }
    if (tid < 204) cbT[79 * CBT_PITCH + tid] = u_base[tid];
    __syncthreads();

    // ---- peak scan + thresholded per-candidate atomic compaction (R12 exact) ----
    const float NEG = -1e30f;
    for (int c = tid; c < HW / 4; c += 1024) {
        int px = c * 4;
        int y  = px / WW;
        int x0 = px - y * WW;
        int ym = (y > 0)      ? y - 1 : y;
        int yp = (y < HH - 1) ? y + 1 : y;
        float4 a0 = *(const float4*)(h + (size_t)ym * WW + x0);
        float4 a1 = *(const float4*)(h + (size_t)y  * WW + x0);
        float4 a2 = *(const float4*)(h + (size_t)yp * WW + x0);
        float m0 = fmaxf(a1.x, fmaxf(a0.x, a2.x));
        float m1 = fmaxf(a1.y, fmaxf(a0.y, a2.y));
        float m2 = fmaxf(a1.z, fmaxf(a0.z, a2.z));
        float m3 = fmaxf(a1.w, fmaxf(a0.w, a2.w));
        float lm = NEG, rm = NEG;
        if (x0 > 0) {
            int xl = x0 - 1;
            lm = fmaxf(h[(size_t)y * WW + xl], fmaxf(h[(size_t)ym * WW + xl], h[(size_t)yp * WW + xl]));
        }
        if (x0 + 4 < WW) {
            int xr = x0 + 4;
            rm = fmaxf(h[(size_t)y * WW + xr], fmaxf(h[(size_t)ym * WW + xr], h[(size_t)yp * WW + xr]));
        }
        bool c0 = (a1.x > THR) && (fmaxf(lm, fmaxf(m0, m1)) == a1.x);
        bool c1 = (a1.y > THR) && (fmaxf(m0, fmaxf(m1, m2)) == a1.y);
        bool c2 = (a1.z > THR) && (fmaxf(m1, fmaxf(m2, m3)) == a1.z);
        bool c3 = (a1.w > THR) && (fmaxf(m2, fmaxf(m3, rm)) == a1.w);
        if (c0) { int pos = atomicAdd(&s_cnt, 1); if (pos < CAPK)
            ck[pos] = ((unsigned long long)__float_as_uint(a1.x) << 20) | (unsigned)(HW - (px + 0)); }
        if (c1) { int pos = atomicAdd(&s_cnt, 1); if (pos < CAPK)
            ck[pos] = ((unsigned long long)__float_as_uint(a1.y) << 20) | (unsigned)(HW - (px + 1)); }
        if (c2) { int pos = atomicAdd(&s_cnt, 1); if (pos < CAPK)
            ck[pos] = ((unsigned long long)__float_as_uint(a1.z) << 20) | (unsigned)(HW - (px + 2)); }
        if (c3) { int pos = atomicAdd(&s_cnt, 1); if (pos < CAPK)
            ck[pos] = ((unsigned long long)__float_as_uint(a1.w) << 20) | (unsigned)(HW - (px + 3)); }
    }
    __syncthreads();

    int cnt = s_cnt;
    bool fast = (cnt >= TOPK) && (cnt <= CAPK);

    if (fast) {
        // direct rank-select over ~250 keys (exact; tie-break in key)
        for (int t = tid; t < cnt; t += 1024) {
            unsigned long long kt = ck[t];
            int rank = 0;
            #pragma unroll 8
            for (int i = 0; i < cnt; i++) rank += (ck[i] > kt) ? 1 : 0;
            if (rank < TOPK) {
                s_sc[rank] = __uint_as_float((unsigned)(kt >> 20));
                s_ix[rank] = HW - (int)(kt & 0xFFFFFull);
            }
        }
    } else {
        // robust fallback: materialize full peak map, 32 block argmax rounds
        float* pk = g_peaks + (size_t)b * HW;
        for (int i = tid; i < HW; i += 1024) {
            int y = i / WW, x = i - y * WW;
            float v = h[i], m = v;
            int y0 = (y > 0) ? y - 1 : y, y1 = (y < HH - 1) ? y + 1 : y;
            int x0 = (x > 0) ? x - 1 : x, x1 = (x < WW - 1) ? x + 1 : x;
            for (int yy = y0; yy <= y1; yy++)
                for (int xx = x0; xx <= x1; xx++)
                    m = fmaxf(m, h[yy * WW + xx]);
            pk[i] = (v == m) ? v : 0.0f;
        }
        __syncthreads();
        for (int r = 0; r < TOPK; r++) {
            float bv = -2.0f; int bi = 0x3fffffff;
            for (int i = tid; i < HW; i += 1024) {
                float v = pk[i];
                if (v > bv || (v == bv && i < bi)) { bv = v; bi = i; }
            }
            #pragma unroll
            for (int o = 16; o; o >>= 1) {
                float v2 = __shfl_down_sync(0xffffffffu, bv, o);
                int   i2 = __shfl_down_sync(0xffffffffu, bi, o);
                if (v2 > bv || (v2 == bv && i2 < bi)) { bv = v2; bi = i2; }
            }
            if (lane == 0) { rv[wid] = bv; rid[wid] = bi; }
            __syncthreads();
            if (tid < 32) {
                bv = rv[lane]; bi = rid[lane];
                #pragma unroll
                for (int o = 16; o; o >>= 1) {
                    float v2 = __shfl_down_sync(0xffffffffu, bv, o);
                    int   i2 = __shfl_down_sync(0xffffffffu, bi, o);
                    if (v2 > bv || (v2 == bv && i2 < bi)) { bv = v2; bi = i2; }
                }
                if (lane == 0) { s_sc[r] = bv; s_ix[r] = bi; pk[bi] = -1.0f; }
            }
            __syncthreads();
        }
    }
    __syncthreads();

    // ================= geometry =================
    for (int e = tid; e < TOPK * 91; e += 1024) {
        int det = e / 91, j = e - det * 91;
        float v = fmaf(pmaps[((size_t)b * HW + (size_t)s_ix[det]) * 91 + j],
                       pms[91 + j], pms[j]);
        int slot = (j < 12) ? (84 + j) : ((j < 62) ? (j - 12) : (52 + (j - 62)));
        sp[det * SP_PITCH + slot] = v;
    }
    __syncthreads();

    // verts: warp w owns rows [8w, 8w+8), lane = det; packed f32x2 FMA
    if (wid < 26) {
        int r0 = wid * 8;
        const float* cp = &sp[lane * SP_PITCH];
        const ulonglong2* urow = (const ulonglong2*)&cbT[79 * CBT_PITCH + r0];
        ulonglong2 u0 = urow[0], u1 = urow[1];
        unsigned long long acc0 = u0.x, acc1 = u0.y, acc2 = u1.x, acc3 = u1.y;
        #pragma unroll 4
        for (int k = 0; k < 79; k++) {
            int slot = k + ((k >= 50) ? 2 : 0);
            float c = cp[slot];
            unsigned long long cd;
            PACK_DUP(cd, c);
            const ulonglong2* brow = (const ulonglong2*)&cbT[k * CBT_PITCH + r0];
            ulonglong2 b0 = brow[0], b1 = brow[1];
            FMA2(acc0, b0.x, cd);
            FMA2(acc1, b0.y, cd);
            FMA2(acc2, b1.x, cd);
            FMA2(acc3, b1.y, cd);
        }
        unsigned av[8];
        UNPACK2(av[0], av[1], acc0);
        UNPACK2(av[2], av[3], acc1);
        UNPACK2(av[4], av[5], acc2);
        UNPACK2(av[6], av[7], acc3);
        #pragma unroll
        for (int q = 0; q < 8; q++) {
            int r = r0 + q;
            if (r < 204) sverts[lane * SV_PITCH + r] = __uint_as_float(av[q]);
        }
    }
    __syncthreads();

    // ---- fused projection + bbox + pose: warp = det (one barrier saved) ----
    {
        int det = wid;
        const float* p = &sp[det * SP_PITCH + 84];
        float s  = p[0];
        float R00 = p[1], R01 = p[2], R02 = p[3];
        float R10 = p[5], R11 = p[6], R12 = p[7];
        int idx = s_ix[det];
        int ys = idx / WW, xs = idx - (idx / WW) * WW;
        float ry = oshapes[b * 2 + 0] * (1.0f / 160.0f);
        float rx = oshapes[b * 2 + 1] * (1.0f / 160.0f);
        float coy = (float)ys * ry;
        float cox = (float)xs * rx;

        float ymn = 1e30f, ymx = -1e30f, xmn = 1e30f, xmx = -1e30f;
        #pragma unroll
        for (int q = 0; q < 3; q++) {
            int v = lane + q * 32;
            if (v < NV) {
                const float* vt = &sverts[det * SV_PITCH + 3 * v];
                float vx = vt[0], vy = vt[1], vz = vt[2];
                float l0 = s * (vx * R00 + vy * R01 + vz * R02);
                float l1 = s * (vx * R10 + vy * R11 + vz * R12);
                float yy = l1 + coy;
                float xx = l0 + cox;
                slnm[det * SL_PITCH + 2 * v]     = yy;
                slnm[det * SL_PITCH + 2 * v + 1] = xx;
                ymn = fminf(ymn, yy); ymx = fmaxf(ymx, yy);
                xmn = fminf(xmn, xx); xmx = fmaxf(xmx, xx);
            }
        }
        #pragma unroll
        for (int o = 16; o; o >>= 1) {
            ymn = fminf(ymn, __shfl_down_sync(0xffffffffu, ymn, o));
            ymx = fmaxf(ymx, __shfl_down_sync(0xffffffffu, ymx, o));
            xmn = fminf(xmn, __shfl_down_sync(0xffffffffu, xmn, o));
            xmx = fmaxf(xmx, __shfl_down_sync(0xffffffffu, xmx, o));
        }
        if (lane == 0) {
            bool mask = s_sc[det] > 0.5f;
            if (mask) { sbb[det][0] = ymn; sbb[det][1] = xmn; sbb[det][2] = ymx; sbb[det][3] = xmx; sbb[det][4] = s_sc[det]; }
            else      { sbb[det][0] = -1.0f; sbb[det][1] = -1.0f; sbb[det][2] = -1.0f; sbb[det][3] = -1.0f; sbb[det][4] = -1.0f; }

            float yaw   = asinf(-p[9]) * RAD2DEG;
            float cyw   = cosf(yaw);   // faithful: cos of yaw in DEGREES
            float pitch = atan2f(p[10] / cyw, p[11] / cyw) * RAD2DEG;
            float roll  = atan2f(R10 / cyw, R00 / cyw) * RAD2DEG;
            spose[det][0] = pitch; spose[det][1] = yaw; spose[det][2] = roll;
        }
    }
    __syncthreads();

    // ================= NMS (parallel row-masks) + packing =================
    if (tid < TOPK) { sosc[tid] = 0.0f; sob[tid][0] = 0.0f; sob[tid][1] = 0.0f; sob[tid][2] = 0.0f; sob[tid][3] = 0.0f; }
    if (tid >= 32 && tid < 64) {
        int i = tid - 32;
        float i0 = sbb[i][0], i1 = sbb[i][1], i2 = sbb[i][2], i3 = sbb[i][3];
        float ia = (i2 - i0) * (i3 - i1);
        unsigned m = 0;
        for (int j = 0; j < TOPK; j++) {
            float j0 = sbb[j][0], j1 = sbb[j][1], j2 = sbb[j][2], j3 = sbb[j][3];
            float ja = (j2 - j0) * (j3 - j1);
            float yy = fminf(i2, j2) - fmaxf(i0, j0);
            float xx = fminf(i3, j3) - fmaxf(i1, j1);
            float inter = fmaxf(yy, 0.0f) * fmaxf(xx, 0.0f);
            float uni   = ia + ja - inter;
            float iou   = inter / fmaxf(uni, 1e-8f);
            if (iou > 0.4f && j > i) m |= (1u << j);
        }
        rowm[i] = m;
    }
    __syncthreads();
    if (tid == 0) {
        unsigned supp = 0u;
        for (int i = 0; i < TOPK; i++)
            if (!((supp >> i) & 1u)) supp |= rowm[i];
        ssupp = supp;
    }
    __syncthreads();
    if (tid < 32) {
        unsigned supp = ssupp;
        bool keep = !((supp >> lane) & 1u);
        unsigned km = __ballot_sync(0xffffffffu, keep);
        int rank = __popc(km & ((1u << lane) - 1u));
        if (keep) {
            sob[rank][0] = sbb[lane][0]; sob[rank][1] = sbb[lane][1];
            sob[rank][2] = sbb[lane][2]; sob[rank][3] = sbb[lane][3];
            sosc[rank]   = sbb[lane][4];
        }
    }
    __syncthreads();

    const float INF = __int_as_float(0x7f800000);
    if (tid < TOPK) {
        bool valid = true;
        #pragma unroll
        for (int c = 0; c < 4; c++) {
            float v = sob[tid][c];
            if (v == -1.0f || v == 0.0f) { v = INF; valid = false; }
            sob[tid][c] = v;
        }
        svalid[tid] = valid ? 1 : 0;
    }
    __syncthreads();
    if (tid < TOPK) {
        float sn = s_sc[tid];
        int m = 0;
        for (int k = 0; k < TOPK; k++)
            if (svalid[k] && sosc[k] == sn) m = 1;
        smatch[tid] = m;
    }
    __syncthreads();

    // out_bboxes (B,32,6)
    float* ob = out + (size_t)b * TOPK * 6;
    for (int e = tid; e < TOPK * 6; e += 1024) {
        int k = e / 6, c = e - k * 6;
        ob[e] = (c < 4) ? sob[k][c] : ((c == 4) ? sosc[k] : 0.0f);
    }
    // out_lnmks (B,32,68,2)
    float* ol = out + (size_t)NB * TOPK * 6 + (size_t)b * TOPK * NV * 2;
    for (int e = tid; e < TOPK * NV * 2; e += 1024) {
        int n = e / (NV * 2), j = e - n * (NV * 2);
        float l = slnm[n * SL_PITCH + j];
        ol[e] = (smatch[n] && l != -1.0f) ? l : INF;
    }
    // out_pose (B,32,3)
    float* op = out + (size_t)NB * TOPK * 6 + (size_t)NB * TOPK * NV * 2 + (size_t)b * TOPK * 3;
    for (int e = tid; e < TOPK * 3; e += 1024) {
        int n = e / 3, c = e - n * 3;
        float p = spose[n][c];
        op[e] = (smatch[n] && p != -1.0f) ? p : INF;
    }
}

extern "C" void kernel_launch(void* const* d_in, const int* in_sizes, int n_in,
                              void* d_out, int out_size) {
    const float* hms      = (const float*)d_in[0];
    const float* pmaps    = (const float*)d_in[1];
    const float* oshapes  = (const float*)d_in[2];
    const float* pms      = (const float*)d_in[3];
    const float* u_base   = (const float*)d_in[4];
    const float* shp_base = (const float*)d_in[5];
    const float* exp_base = (const float*)d_in[6];
    float* out = (float*)d_out;

    static int attr_done = 0;
    if (!attr_done) {
        cudaFuncSetAttribute(fused_kernel, cudaFuncAttributeMaxDynamicSharedMemorySize, DSM_SIZE);
        attr_done = 1;
    }
    fused_kernel<<<NB, 1024, DSM_SIZE>>>(hms, pmaps, oshapes, pms, u_base, shp_base, exp_base, out);
}